// round 13
// baseline (speedup 1.0000x reference)
#include <cuda_runtime.h>
#include <cuda_fp16.h>

// GPTQ int4 dequant GEMM via HMMA: out[32,8192] = x @ dequant(W)^T + bias
// M=32, K=8192, N=8192, group=64. packed int32 element = one byte = 2 k-nibbles.
// v13: v11 core (raw biased nibbles 1024+q, running rescale fixup, XOR swizzle)
// with KSPLIT=32 (KPER=256): smem 53.8KB/CTA -> 4 CTAs/SM (32 warps, +33%
// latency hiding), grid 2048. __launch_bounds__(256,4) caps regs at 64.

#define MM 32
#define KDIM 8192
#define NDIM 8192
#define GS 64
#define NGROUPS 128
#define NTHREADS 256
#define NBLK 128           // n per CTA
#define KSPLIT 32
#define KPER 256           // k per CTA
#define GROUPS_PER 4       // KPER / GS
#define WGRP 4096          // int32 per group buffer: 128 rows * 32 int32
#define WS_BYTES (2 * WGRP * 4)          // 32768
#define XROWB 512          // bytes per xs row (256 k * 2B, swizzled, no pad)
#define XS_BYTES (MM * XROWB)            // 16384
#define SMEM_TOTAL (WS_BYTES + XS_BYTES + 512 + 2 * GROUPS_PER * NBLK * 4) // 53760

// global LUT: X_g[m] = sum_{k in group g} fp16(x[m,k]), fp32. 16 KB.
__device__ float d_Xg[NGROUPS * MM];

__device__ __forceinline__ unsigned smem_u32(const void* p) {
    unsigned a;
    asm("{ .reg .u64 t; cvta.to.shared.u64 t, %1; cvt.u32.u64 %0, t; }"
        : "=r"(a) : "l"(p));
    return a;
}
__device__ __forceinline__ void cp_async16(unsigned saddr, const void* gptr) {
    asm volatile("cp.async.cg.shared.global [%0], [%1], 16;\n"
                 :: "r"(saddr), "l"(gptr));
}
__device__ __forceinline__ void cp_commit() {
    asm volatile("cp.async.commit_group;\n" ::: "memory");
}
template <int N>
__device__ __forceinline__ void cp_wait() {
    asm volatile("cp.async.wait_group %0;\n" :: "n"(N) : "memory");
}
__device__ __forceinline__ void ldsm4(unsigned& r0, unsigned& r1,
                                      unsigned& r2, unsigned& r3, unsigned a) {
    asm volatile("ldmatrix.sync.aligned.m8n8.x4.shared.b16 {%0,%1,%2,%3}, [%4];"
                 : "=r"(r0), "=r"(r1), "=r"(r2), "=r"(r3) : "r"(a));
}
__device__ __forceinline__ void mma16816(float d[4], const unsigned a[4],
                                         const unsigned b[2]) {
    asm volatile(
        "mma.sync.aligned.m16n8k16.row.col.f32.f16.f16.f32 "
        "{%0,%1,%2,%3}, {%4,%5,%6,%7}, {%8,%9}, {%0,%1,%2,%3};"
        : "+f"(d[0]), "+f"(d[1]), "+f"(d[2]), "+f"(d[3])
        : "r"(a[0]), "r"(a[1]), "r"(a[2]), "r"(a[3]), "r"(b[0]), "r"(b[1]));
}
__device__ __forceinline__ void red2(float* p, float a, float b) {
    asm volatile("red.global.add.v2.f32 [%0], {%1, %2};"
                 :: "l"(p), "f"(a), "f"(b) : "memory");
}
// raw biased dequant: byte b -> fp16x2 {lo = 1024+lo_nib, hi = 1024+hi_nib}. Exact.
__device__ __forceinline__ unsigned dqraw(int b) {
    unsigned t = (unsigned)b | ((unsigned)b << 12);
    return (t & 0x000F000Fu) | 0x64006400u;
}

// merged prologue: blocks 0..255 init out=bias (float4); blocks 256..287 X sums
__global__ void __launch_bounds__(NTHREADS)
gptq_pre(const float* __restrict__ bias, float* __restrict__ out,
         const float* __restrict__ x) {
    const int bid = blockIdx.x;
    const int t = threadIdx.x;
    const int NINIT = (MM * NDIM / 4) / NTHREADS;   // 256
    if (bid < NINIT) {
        int i = bid * NTHREADS + t;                 // float4 index
        const float4* b4 = reinterpret_cast<const float4*>(bias);
        reinterpret_cast<float4*>(out)[i] = b4[i & (NDIM / 4 - 1)];
        return;
    }
    const int m = bid - NINIT;
    const int l = t & 31;
    const float4* xr = reinterpret_cast<const float4*>(x + (size_t)m * KDIM);
    float s[8];
#pragma unroll
    for (int i = 0; i < 8; ++i) {
        float4 v = xr[t + 256 * i];
        __half2 h0 = __floats2half2_rn(v.x, v.y);
        __half2 h1 = __floats2half2_rn(v.z, v.w);
        float2 f0 = __half22float2(h0);
        float2 f1 = __half22float2(h1);
        s[i] = (f0.x + f0.y) + (f1.x + f1.y);
    }
#pragma unroll
    for (int mask = 1; mask < 16; mask <<= 1)
#pragma unroll
        for (int i = 0; i < 8; ++i)
            s[i] += __shfl_xor_sync(0xFFFFFFFFu, s[i], mask);
    const int j = l & 15;
    if (j < 8) {
        const int g = (t >> 4) + 16 * j;
        d_Xg[g * MM + m] = s[j];
    }
}

extern __shared__ char smem_raw[];

__global__ void __launch_bounds__(NTHREADS, 4)
gptq_main(const float* __restrict__ x, const int* __restrict__ pw,
          const float* __restrict__ scales, const float* __restrict__ zeros,
          float* __restrict__ out)
{
    int* ws = reinterpret_cast<int*>(smem_raw);                        // [2][128][32], swizzled
    __half* xs = reinterpret_cast<__half*>(smem_raw + WS_BYTES);       // [32][256], swizzled
    float* xsum = reinterpret_cast<float*>(smem_raw + WS_BYTES + XS_BYTES); // [4][32]
    float* c2s = xsum + GROUPS_PER * 32;                               // [4][128] z+1024
    float* rqs = c2s + GROUPS_PER * NBLK;                              // [4][128] ratio

    const int tid = threadIdx.x;
    const int w = tid >> 5;
    const int l = tid & 31;
    const int nblock0 = blockIdx.x * NBLK;
    const int k0 = blockIdx.y * KPER;
    const int g0 = blockIdx.y * GROUPS_PER;

    const unsigned ws_base = smem_u32(ws);

    // weight staging (v11 geometry): thread -> (row = tid>>3 + 32i, ch = tid&7),
    // swizzled chunk = ch ^ (row&7).
    const int s_ch  = tid & 7;
    const int s_row = tid >> 3;
    const int s_swz = s_ch ^ (s_row & 7);

    auto stage_w = [&](int g, int b) {
        const int* gsrc = pw + ((k0 + g * GS) >> 1) + s_ch * 4;
        unsigned sdst = ws_base + (unsigned)(b * WGRP * 4 + s_row * 128 + s_swz * 16);
#pragma unroll
        for (int i = 0; i < 4; ++i)
            cp_async16(sdst + (unsigned)(i * 32 * 128),
                       gsrc + (size_t)(nblock0 + s_row + i * 32) * (KDIM / 2));
        cp_commit();
    };
    stage_w(0, 0);
    stage_w(1, 1);

    // ---- stage x: fp32 -> fp16, swizzled 512B rows (chunk16 ^= m&7) ----
    {
#pragma unroll
        for (int i = 0; i < 8; ++i) {
            int lin = tid + i * NTHREADS;  // 0..2047 float4s
            int v = lin & 63;              // float4 idx along k
            int m = lin >> 6;
            float4 xv = *reinterpret_cast<const float4*>(x + (size_t)m * KDIM + k0 + 4 * v);
            __half2 h0 = __floats2half2_rn(xv.x, xv.y);
            __half2 h1 = __floats2half2_rn(xv.z, xv.w);
            uint2 pr;
            pr.x = *reinterpret_cast<unsigned*>(&h0);
            pr.y = *reinterpret_cast<unsigned*>(&h1);
            unsigned byte_off = (unsigned)(m * XROWB + (((v >> 1) ^ (m & 7)) << 4) + (v & 1) * 8);
            *reinterpret_cast<uint2*>(reinterpret_cast<char*>(xs) + byte_off) = pr;
        }
    }

    // ---- X LUT slice: 128 entries (4 groups x 32 m) ----
    if (tid < GROUPS_PER * 32)
        xsum[tid] = __ldg(&d_Xg[(g0 + (tid >> 5)) * MM + (tid & 31)]);

    // ---- scale/zero LUTs: c2[g][n] = z+1024; rq = s_g/s_{g+1} (g<3), s_3 (g==3) ----
#pragma unroll
    for (int i = 0; i < 2; ++i) {
        int lin = tid + i * NTHREADS;   // 0..511
        int g = lin & 3;
        int n = lin >> 2;               // 0..127
        const float* srow = scales + (size_t)(nblock0 + n) * NGROUPS + g0;
        float s = __ldg(srow + g);
        float z = __ldg(zeros + (size_t)(nblock0 + n) * NGROUPS + g0 + g);
        float rq;
        if (g < GROUPS_PER - 1) {
            float sn = __ldg(srow + g + 1);
            rq = __fdividef(s, sn);
        } else {
            rq = s;
        }
        c2s[g * NBLK + n] = z + 1024.0f;
        rqs[g * NBLK + n] = rq;
    }

    // lane geometry (v11)
    const unsigned xs_base = smem_u32(xs);
    const unsigned xrow0 = xs_base + (unsigned)((l & 15) * XROWB);
    const unsigned xrow1 = xrow0 + 16u * XROWB;
    const int hk = l >> 4;
    const int lw = l & 7;
    const int xw = l >> 2;
    const int wbase0 = (w * 16 + (l >> 2)) * 32 + (l & 3);
    const int wbase1 = wbase0 + 8 * 32;
    const int ncol = w * 16 + 2 * (l & 3);

    float acc[2][2][4] = {};

#pragma unroll
    for (int g = 0; g < GROUPS_PER; ++g) {
        if (g == GROUPS_PER - 1) cp_wait<0>(); else cp_wait<1>();
        __syncthreads();

        const int bufo = (g & 1) * WGRP;

#pragma unroll
        for (int s4 = 0; s4 < 4; ++s4) {
            const int s = g * 4 + s4;          // global k16-step 0..15
            unsigned xoff = (unsigned)(((2 * s + hk) ^ lw) << 4);
            unsigned a0[4], a1[4];
            ldsm4(a0[0], a0[1], a0[2], a0[3], xrow0 + xoff);
            ldsm4(a1[0], a1[1], a1[2], a1[3], xrow1 + xoff);

            const int c0 = ((2 * s4)     ^ xw) * 4;
            const int c1 = ((2 * s4 + 1) ^ xw) * 4;
            unsigned b0[2], b1[2];
            b0[0] = dqraw(ws[bufo + wbase0 + c0]);
            b0[1] = dqraw(ws[bufo + wbase0 + c1]);
            b1[0] = dqraw(ws[bufo + wbase1 + c0]);
            b1[1] = dqraw(ws[bufo + wbase1 + c1]);

            mma16816(acc[0][0], a0, b0);
            mma16816(acc[0][1], a0, b1);
            mma16816(acc[1][0], a1, b0);
            mma16816(acc[1][1], a1, b1);
        }

        // end-of-group fixup: acc = (acc - (z+1024)*X_g[row]) * rq
        {
            const float* xg = xsum + g * 32 + (l >> 2);
            float Xv[4];
            Xv[0] = xg[0];  Xv[1] = xg[8];
            Xv[2] = xg[16]; Xv[3] = xg[24];
            const float* c2g = c2s + g * NBLK + ncol;
            const float* rqg = rqs + g * NBLK + ncol;
            float c2v[4], rqv[4];
            c2v[0] = c2g[0]; c2v[1] = c2g[1]; c2v[2] = c2g[8]; c2v[3] = c2g[9];
            rqv[0] = rqg[0]; rqv[1] = rqg[1]; rqv[2] = rqg[8]; rqv[3] = rqg[9];
#pragma unroll
            for (int tm = 0; tm < 2; ++tm)
#pragma unroll
                for (int tn = 0; tn < 2; ++tn)
#pragma unroll
                    for (int e = 0; e < 4; ++e) {
                        const float Xe = Xv[tm * 2 + (e >> 1)];
                        const float c2e = c2v[tn * 2 + (e & 1)];
                        const float rqe = rqv[tn * 2 + (e & 1)];
                        acc[tm][tn][e] = fmaf(-c2e, Xe, acc[tm][tn][e]) * rqe;
                    }
        }

        if (g < GROUPS_PER - 2) {
            __syncthreads();           // all warps done reading buffer g&1
            stage_w(g + 2, g & 1);
        }
    }

    // ---- epilogue: K-split partials via vector reductions ----
#pragma unroll
    for (int tm = 0; tm < 2; ++tm) {
#pragma unroll
        for (int tn = 0; tn < 2; ++tn) {
            const int n = nblock0 + w * 16 + tn * 8 + (l & 3) * 2;
            const int m = tm * 16 + (l >> 2);
            red2(out + (size_t)m * NDIM + n,       acc[tm][tn][0], acc[tm][tn][1]);
            red2(out + (size_t)(m + 8) * NDIM + n, acc[tm][tn][2], acc[tm][tn][3]);
        }
    }
}

extern "C" void kernel_launch(void* const* d_in, const int* in_sizes, int n_in,
                              void* d_out, int out_size) {
    const float* x      = (const float*)d_in[0];
    const int*   pw     = (const int*)d_in[1];
    const float* scales = (const float*)d_in[2];
    const float* zeros  = (const float*)d_in[3];
    const float* bias   = (const float*)d_in[4];
    float* out = (float*)d_out;

    gptq_pre<<<(MM * NDIM / 4) / NTHREADS + MM, NTHREADS>>>(bias, out, x);

    cudaFuncSetAttribute(gptq_main, cudaFuncAttributeMaxDynamicSharedMemorySize,
                         SMEM_TOTAL);
    dim3 grid(NDIM / NBLK, KSPLIT);
    gptq_main<<<grid, NTHREADS, SMEM_TOTAL>>>(x, pw, scales, zeros, out);
}

// round 14
// speedup vs baseline: 1.0241x; 1.0241x over previous
#include <cuda_runtime.h>
#include <cuda_fp16.h>

// GPTQ int4 dequant GEMM via HMMA: out[32,8192] = x @ dequant(W)^T + bias
// M=32, K=8192, N=8192, group=64. packed int32 element = one byte = 2 k-nibbles.
// v14: v11 config (3 CTAs/SM, KSPLIT=16, XOR swizzle, raw biased nibbles 1024+q,
// running rescale fixup) with (a) STAGGERED weight staging -- each group's 16KB
// split into two 8KB half-commits issued at different times (end of group g-2,
// mid group g-1) to halve peak L1tex LDGSTS queue depth; (b) x pre-converted to
// fp16 by the pre-kernel (same rounding as X sums) and staged via cp.async.

#define MM 32
#define KDIM 8192
#define NDIM 8192
#define GS 64
#define NGROUPS 128
#define NTHREADS 256
#define NBLK 128           // n per CTA
#define KSPLIT 16
#define KPER 512           // k per CTA
#define GROUPS_PER 8       // KPER / GS
#define WGRP 4096          // int32 per group buffer: 128 rows * 32 int32
#define WS_BYTES (2 * WGRP * 4)          // 32768
#define XROWB 1024         // bytes per xs row (512 k * 2B, swizzled, no pad)
#define XS_BYTES (MM * XROWB)            // 32768
#define SMEM_TOTAL (WS_BYTES + XS_BYTES + 1024 + 2 * GROUPS_PER * NBLK * 4) // 74752

// global LUTs from pre-kernel
__device__ float  d_Xg[NGROUPS * MM];        // X_g[m] = sum_{k in g} fp16(x[m,k])
__device__ __half d_x16[MM * KDIM];          // fp16(x), same rounding as d_Xg

__device__ __forceinline__ unsigned smem_u32(const void* p) {
    unsigned a;
    asm("{ .reg .u64 t; cvta.to.shared.u64 t, %1; cvt.u32.u64 %0, t; }"
        : "=r"(a) : "l"(p));
    return a;
}
__device__ __forceinline__ void cp_async16(unsigned saddr, const void* gptr) {
    asm volatile("cp.async.cg.shared.global [%0], [%1], 16;\n"
                 :: "r"(saddr), "l"(gptr));
}
__device__ __forceinline__ void cp_commit() {
    asm volatile("cp.async.commit_group;\n" ::: "memory");
}
template <int N>
__device__ __forceinline__ void cp_wait() {
    asm volatile("cp.async.wait_group %0;\n" :: "n"(N) : "memory");
}
__device__ __forceinline__ void ldsm4(unsigned& r0, unsigned& r1,
                                      unsigned& r2, unsigned& r3, unsigned a) {
    asm volatile("ldmatrix.sync.aligned.m8n8.x4.shared.b16 {%0,%1,%2,%3}, [%4];"
                 : "=r"(r0), "=r"(r1), "=r"(r2), "=r"(r3) : "r"(a));
}
__device__ __forceinline__ void mma16816(float d[4], const unsigned a[4],
                                         const unsigned b[2]) {
    asm volatile(
        "mma.sync.aligned.m16n8k16.row.col.f32.f16.f16.f32 "
        "{%0,%1,%2,%3}, {%4,%5,%6,%7}, {%8,%9}, {%0,%1,%2,%3};"
        : "+f"(d[0]), "+f"(d[1]), "+f"(d[2]), "+f"(d[3])
        : "r"(a[0]), "r"(a[1]), "r"(a[2]), "r"(a[3]), "r"(b[0]), "r"(b[1]));
}
__device__ __forceinline__ void red2(float* p, float a, float b) {
    asm volatile("red.global.add.v2.f32 [%0], {%1, %2};"
                 :: "l"(p), "f"(a), "f"(b) : "memory");
}
// raw biased dequant: byte b -> fp16x2 {lo = 1024+lo_nib, hi = 1024+hi_nib}. Exact.
__device__ __forceinline__ unsigned dqraw(int b) {
    unsigned t = (unsigned)b | ((unsigned)b << 12);
    return (t & 0x000F000Fu) | 0x64006400u;
}

// merged prologue: blocks 0..255 init out=bias (float4); blocks 256..287:
// per-m X group sums + fp16 conversion of x (identical rounding).
__global__ void __launch_bounds__(NTHREADS)
gptq_pre(const float* __restrict__ bias, float* __restrict__ out,
         const float* __restrict__ x) {
    const int bid = blockIdx.x;
    const int t = threadIdx.x;
    const int NINIT = (MM * NDIM / 4) / NTHREADS;   // 256
    if (bid < NINIT) {
        int i = bid * NTHREADS + t;                 // float4 index
        const float4* b4 = reinterpret_cast<const float4*>(bias);
        reinterpret_cast<float4*>(out)[i] = b4[i & (NDIM / 4 - 1)];
        return;
    }
    const int m = bid - NINIT;
    const int l = t & 31;
    const float4* xr = reinterpret_cast<const float4*>(x + (size_t)m * KDIM);
    uint2* x16r = reinterpret_cast<uint2*>(d_x16 + (size_t)m * KDIM);
    float s[8];
#pragma unroll
    for (int i = 0; i < 8; ++i) {
        float4 v = xr[t + 256 * i];
        __half2 h0 = __floats2half2_rn(v.x, v.y);
        __half2 h1 = __floats2half2_rn(v.z, v.w);
        uint2 pr;
        pr.x = *reinterpret_cast<unsigned*>(&h0);
        pr.y = *reinterpret_cast<unsigned*>(&h1);
        x16r[t + 256 * i] = pr;                     // 8B = 4 halfs per float4
        float2 f0 = __half22float2(h0);
        float2 f1 = __half22float2(h1);
        s[i] = (f0.x + f0.y) + (f1.x + f1.y);
    }
#pragma unroll
    for (int mask = 1; mask < 16; mask <<= 1)
#pragma unroll
        for (int i = 0; i < 8; ++i)
            s[i] += __shfl_xor_sync(0xFFFFFFFFu, s[i], mask);
    const int j = l & 15;
    if (j < 8) {
        const int g = (t >> 4) + 16 * j;
        d_Xg[g * MM + m] = s[j];
    }
}

extern __shared__ char smem_raw[];

__global__ void __launch_bounds__(NTHREADS, 3)
gptq_main(const int* __restrict__ pw,
          const float* __restrict__ scales, const float* __restrict__ zeros,
          float* __restrict__ out)
{
    int* ws = reinterpret_cast<int*>(smem_raw);                        // [2][128][32], swizzled
    __half* xs = reinterpret_cast<__half*>(smem_raw + WS_BYTES);       // [32][512], swizzled
    float* xsum = reinterpret_cast<float*>(smem_raw + WS_BYTES + XS_BYTES); // [8][32]
    float* c2s = xsum + GROUPS_PER * 32;                               // [8][128] z+1024
    float* rqs = c2s + GROUPS_PER * NBLK;                              // [8][128] ratio

    const int tid = threadIdx.x;
    const int w = tid >> 5;
    const int l = tid & 31;
    const int nblock0 = blockIdx.x * NBLK;
    const int k0 = blockIdx.y * KPER;
    const int g0 = blockIdx.y * GROUPS_PER;

    const unsigned ws_base = smem_u32(ws);
    const unsigned xs_base = smem_u32(xs);

    // weight staging geometry: thread -> (row = tid>>3 (+32i), ch = tid&7),
    // swizzled chunk = ch ^ (row&7).
    const int s_ch  = tid & 7;
    const int s_row = tid >> 3;
    const int s_swz = s_ch ^ (s_row & 7);

    // stage HALF h (0: rows 0-63, 1: rows 64-127) of group g into buffer b; 8KB.
    auto stage_wh = [&](int g, int b, int h) {
        const int* gsrc = pw + ((k0 + g * GS) >> 1) + s_ch * 4;
        unsigned sdst = ws_base + (unsigned)(b * WGRP * 4 + s_row * 128 + s_swz * 16);
#pragma unroll
        for (int i = 0; i < 2; ++i) {
            int r = h * 64 + i * 32;
            cp_async16(sdst + (unsigned)(r * 128),
                       gsrc + (size_t)(nblock0 + s_row + r) * (KDIM / 2));
        }
        cp_commit();
    };

    // ---- commit C1: x via cp.async from pre-converted fp16 (swizzled dst) ----
    {
        const int xm = tid >> 3;           // m row 0..31
        const int xc = tid & 7;            // base chunk; chunks xc + 8j, j<8
        const __half* gx = d_x16 + (size_t)xm * KDIM + k0;
        unsigned dbase = xs_base + (unsigned)(xm * XROWB);
        const int msw = xm & 7;
#pragma unroll
        for (int j = 0; j < 8; ++j) {
            int c = xc + 8 * j;            // 16B chunk index along k (64 per row)
            cp_async16(dbase + (unsigned)(((c ^ msw) & 63) << 4), gx + c * 8);
        }
        cp_commit();
    }
    // ---- commits C2..C4: weights group0 (both halves) + group1 half0 ----
    stage_wh(0, 0, 0);
    stage_wh(0, 0, 1);
    stage_wh(1, 1, 0);

    // ---- X LUT slice (overlaps cp.async) ----
    xsum[tid] = __ldg(&d_Xg[(g0 + (tid >> 5)) * MM + (tid & 31)]);

    // ---- scale/zero LUTs ----
#pragma unroll
    for (int i = 0; i < 4; ++i) {
        int lin = tid + i * NTHREADS;   // 0..1023
        int g = lin & 7;
        int n = lin >> 3;               // 0..127
        const float* srow = scales + (size_t)(nblock0 + n) * NGROUPS + g0;
        float s = __ldg(srow + g);
        float z = __ldg(zeros + (size_t)(nblock0 + n) * NGROUPS + g0 + g);
        float rq;
        if (g < GROUPS_PER - 1) {
            float sn = __ldg(srow + g + 1);
            rq = __fdividef(s, sn);
        } else {
            rq = s;
        }
        c2s[g * NBLK + n] = z + 1024.0f;
        rqs[g * NBLK + n] = rq;
    }

    // lane geometry (v11)
    const unsigned xrow0 = xs_base + (unsigned)((l & 15) * XROWB);
    const unsigned xrow1 = xrow0 + 16u * XROWB;
    const int hk = l >> 4;
    const int lw = l & 7;
    const int xw = l >> 2;
    const int wbase0 = (w * 16 + (l >> 2)) * 32 + (l & 3);
    const int wbase1 = wbase0 + 8 * 32;
    const int ncol = w * 16 + 2 * (l & 3);

    float acc[2][2][4] = {};

#pragma unroll
    for (int g = 0; g < GROUPS_PER; ++g) {
        // commit stream (steady state): [.., g.h1, g+1.h0] pending at entry.
        // wait<1> leaves only the newest (g+1.h0) outstanding -> group g done
        // (and for g==0 also the x commit). Last group: nothing newer -> wait<0>.
        if (g == GROUPS_PER - 1) cp_wait<0>(); else cp_wait<1>();
        __syncthreads();

        const int bufo = (g & 1) * WGRP;

#pragma unroll
        for (int s4 = 0; s4 < 4; ++s4) {
            const int s = g * 4 + s4;          // global k16-step
            unsigned xoff = (unsigned)(((2 * s + hk) ^ lw) << 4);
            unsigned a0[4], a1[4];
            ldsm4(a0[0], a0[1], a0[2], a0[3], xrow0 + xoff);
            ldsm4(a1[0], a1[1], a1[2], a1[3], xrow1 + xoff);

            const int c0 = ((2 * s4)     ^ xw) * 4;
            const int c1 = ((2 * s4 + 1) ^ xw) * 4;
            unsigned b0[2], b1[2];
            b0[0] = dqraw(ws[bufo + wbase0 + c0]);
            b0[1] = dqraw(ws[bufo + wbase0 + c1]);
            b1[0] = dqraw(ws[bufo + wbase1 + c0]);
            b1[1] = dqraw(ws[bufo + wbase1 + c1]);

            mma16816(acc[0][0], a0, b0);
            mma16816(acc[0][1], a0, b1);
            mma16816(acc[1][0], a1, b0);
            mma16816(acc[1][1], a1, b1);

            // mid-group: issue SECOND half of group g+1 into its (in-flight,
            // unread) buffer. De-bursts the LDGSTS stream vs one 16KB blast.
            if (s4 == 1 && g + 1 < GROUPS_PER)
                stage_wh(g + 1, (g + 1) & 1, 1);
        }

        // end-of-group fixup: acc = (acc - (z+1024)*X_g[row]) * rq
        {
            const float* xg = xsum + g * 32 + (l >> 2);
            float Xv[4];
            Xv[0] = xg[0];  Xv[1] = xg[8];
            Xv[2] = xg[16]; Xv[3] = xg[24];
            const float* c2g = c2s + g * NBLK + ncol;
            const float* rqg = rqs + g * NBLK + ncol;
            float c2v[4], rqv[4];
            c2v[0] = c2g[0]; c2v[1] = c2g[1]; c2v[2] = c2g[8]; c2v[3] = c2g[9];
            rqv[0] = rqg[0]; rqv[1] = rqg[1]; rqv[2] = rqg[8]; rqv[3] = rqg[9];
#pragma unroll
            for (int tm = 0; tm < 2; ++tm)
#pragma unroll
                for (int tn = 0; tn < 2; ++tn)
#pragma unroll
                    for (int e = 0; e < 4; ++e) {
                        const float Xe = Xv[tm * 2 + (e >> 1)];
                        const float c2e = c2v[tn * 2 + (e & 1)];
                        const float rqe = rqv[tn * 2 + (e & 1)];
                        acc[tm][tn][e] = fmaf(-c2e, Xe, acc[tm][tn][e]) * rqe;
                    }
        }

        if (g + 2 < GROUPS_PER) {
            __syncthreads();               // all warps done reading buffer g&1
            stage_wh(g + 2, g & 1, 0);     // first half now; second half lands
                                           // mid-group g+1 (stagger)
        }
    }

    // ---- epilogue: K-split partials via vector reductions ----
#pragma unroll
    for (int tm = 0; tm < 2; ++tm) {
#pragma unroll
        for (int tn = 0; tn < 2; ++tn) {
            const int n = nblock0 + w * 16 + tn * 8 + (l & 3) * 2;
            const int m = tm * 16 + (l >> 2);
            red2(out + (size_t)m * NDIM + n,       acc[tm][tn][0], acc[tm][tn][1]);
            red2(out + (size_t)(m + 8) * NDIM + n, acc[tm][tn][2], acc[tm][tn][3]);
        }
    }
}

extern "C" void kernel_launch(void* const* d_in, const int* in_sizes, int n_in,
                              void* d_out, int out_size) {
    const float* x      = (const float*)d_in[0];
    const int*   pw     = (const int*)d_in[1];
    const float* scales = (const float*)d_in[2];
    const float* zeros  = (const float*)d_in[3];
    const float* bias   = (const float*)d_in[4];
    float* out = (float*)d_out;

    gptq_pre<<<(MM * NDIM / 4) / NTHREADS + MM, NTHREADS>>>(bias, out, x);

    cudaFuncSetAttribute(gptq_main, cudaFuncAttributeMaxDynamicSharedMemorySize,
                         SMEM_TOTAL);
    dim3 grid(NDIM / NBLK, KSPLIT);
    gptq_main<<<grid, NTHREADS, SMEM_TOTAL>>>(pw, scales, zeros, out);
}

// round 15
// speedup vs baseline: 1.0744x; 1.0491x over previous
#include <cuda_runtime.h>
#include <cuda_fp16.h>

// GPTQ int4 dequant GEMM via HMMA: out[32,8192] = x @ dequant(W)^T + bias
// M=32, K=8192, N=8192, group=64. packed int32 element = one byte = 2 k-nibbles.
// v15: v11 mainloop verbatim (best: 36.9us). Pre-kernel deleted:
//   - out zeroed by cudaMemsetAsync (graph memset node), bias added in epilogue
//     by blockIdx.y==0 CTAs before red2;
//   - X_g[m] = sum fp16(x) computed IN-CTA from the staged fp16 xs tile
//     (one LDS pass, ~70 issues/thread, once) instead of a global LUT.

#define MM 32
#define KDIM 8192
#define NDIM 8192
#define GS 64
#define NGROUPS 128
#define NTHREADS 256
#define NBLK 128           // n per CTA
#define KSPLIT 16
#define KPER 512           // k per CTA
#define GROUPS_PER 8       // KPER / GS
#define WGRP 4096          // int32 per group buffer: 128 rows * 32 int32
#define WS_BYTES (2 * WGRP * 4)          // 32768
#define XROWB 1024         // bytes per xs row (512 k * 2B, swizzled, no pad)
#define XS_BYTES (MM * XROWB)            // 32768
#define SMEM_TOTAL (WS_BYTES + XS_BYTES + 1024 + 2 * GROUPS_PER * NBLK * 4) // 74752

__device__ __forceinline__ unsigned smem_u32(const void* p) {
    unsigned a;
    asm("{ .reg .u64 t; cvta.to.shared.u64 t, %1; cvt.u32.u64 %0, t; }"
        : "=r"(a) : "l"(p));
    return a;
}
__device__ __forceinline__ void cp_async16(unsigned saddr, const void* gptr) {
    asm volatile("cp.async.cg.shared.global [%0], [%1], 16;\n"
                 :: "r"(saddr), "l"(gptr));
}
__device__ __forceinline__ void cp_commit() {
    asm volatile("cp.async.commit_group;\n" ::: "memory");
}
template <int N>
__device__ __forceinline__ void cp_wait() {
    asm volatile("cp.async.wait_group %0;\n" :: "n"(N) : "memory");
}
__device__ __forceinline__ void ldsm4(unsigned& r0, unsigned& r1,
                                      unsigned& r2, unsigned& r3, unsigned a) {
    asm volatile("ldmatrix.sync.aligned.m8n8.x4.shared.b16 {%0,%1,%2,%3}, [%4];"
                 : "=r"(r0), "=r"(r1), "=r"(r2), "=r"(r3) : "r"(a));
}
__device__ __forceinline__ void mma16816(float d[4], const unsigned a[4],
                                         const unsigned b[2]) {
    asm volatile(
        "mma.sync.aligned.m16n8k16.row.col.f32.f16.f16.f32 "
        "{%0,%1,%2,%3}, {%4,%5,%6,%7}, {%8,%9}, {%0,%1,%2,%3};"
        : "+f"(d[0]), "+f"(d[1]), "+f"(d[2]), "+f"(d[3])
        : "r"(a[0]), "r"(a[1]), "r"(a[2]), "r"(a[3]), "r"(b[0]), "r"(b[1]));
}
__device__ __forceinline__ void red2(float* p, float a, float b) {
    asm volatile("red.global.add.v2.f32 [%0], {%1, %2};"
                 :: "l"(p), "f"(a), "f"(b) : "memory");
}
// raw biased dequant: byte b -> fp16x2 {lo = 1024+lo_nib, hi = 1024+hi_nib}. Exact.
__device__ __forceinline__ unsigned dqraw(int b) {
    unsigned t = (unsigned)b | ((unsigned)b << 12);
    return (t & 0x000F000Fu) | 0x64006400u;
}

extern __shared__ char smem_raw[];

__global__ void __launch_bounds__(NTHREADS, 3)
gptq_main(const float* __restrict__ x, const int* __restrict__ pw,
          const float* __restrict__ scales, const float* __restrict__ zeros,
          const float* __restrict__ bias, float* __restrict__ out)
{
    int* ws = reinterpret_cast<int*>(smem_raw);                        // [2][128][32], swizzled
    __half* xs = reinterpret_cast<__half*>(smem_raw + WS_BYTES);       // [32][512], swizzled
    float* xsum = reinterpret_cast<float*>(smem_raw + WS_BYTES + XS_BYTES); // [8][32]
    float* c2s = xsum + GROUPS_PER * 32;                               // [8][128] z+1024
    float* rqs = c2s + GROUPS_PER * NBLK;                              // [8][128] ratio

    const int tid = threadIdx.x;
    const int w = tid >> 5;
    const int l = tid & 31;
    const int nblock0 = blockIdx.x * NBLK;
    const int k0 = blockIdx.y * KPER;
    const int g0 = blockIdx.y * GROUPS_PER;

    const unsigned ws_base = smem_u32(ws);

    // weight staging (v11 geometry): thread -> (row = tid>>3 + 32i, ch = tid&7),
    // swizzled chunk = ch ^ (row&7).
    const int s_ch  = tid & 7;
    const int s_row = tid >> 3;
    const int s_swz = s_ch ^ (s_row & 7);

    auto stage_w = [&](int g, int b) {
        const int* gsrc = pw + ((k0 + g * GS) >> 1) + s_ch * 4;
        unsigned sdst = ws_base + (unsigned)(b * WGRP * 4 + s_row * 128 + s_swz * 16);
#pragma unroll
        for (int i = 0; i < 4; ++i)
            cp_async16(sdst + (unsigned)(i * 32 * 128),
                       gsrc + (size_t)(nblock0 + s_row + i * 32) * (KDIM / 2));
        cp_commit();
    };
    stage_w(0, 0);
    stage_w(1, 1);

    // ---- stage x: fp32 -> fp16, swizzled 1024B rows (chunk16 ^= m&7) ----
    {
#pragma unroll
        for (int i = 0; i < 16; ++i) {
            int lin = tid + i * NTHREADS;  // 0..4095 float4s
            int v = lin & 127;             // float4 idx along k (8B unit)
            int m = lin >> 7;
            float4 xv = *reinterpret_cast<const float4*>(x + (size_t)m * KDIM + k0 + 4 * v);
            __half2 h0 = __floats2half2_rn(xv.x, xv.y);
            __half2 h1 = __floats2half2_rn(xv.z, xv.w);
            uint2 pr;
            pr.x = *reinterpret_cast<unsigned*>(&h0);
            pr.y = *reinterpret_cast<unsigned*>(&h1);
            unsigned byte_off = (unsigned)(m * XROWB + (((v >> 1) ^ (m & 7)) << 4) + (v & 1) * 8);
            *reinterpret_cast<uint2*>(reinterpret_cast<char*>(xs) + byte_off) = pr;
        }
    }

    // ---- scale/zero LUTs: c2[g][n] = z+1024; rq = s_g/s_{g+1} (g<7), s_7 (g==7) ----
#pragma unroll
    for (int i = 0; i < 4; ++i) {
        int lin = tid + i * NTHREADS;   // 0..1023
        int g = lin & 7;
        int n = lin >> 3;               // 0..127
        const float* srow = scales + (size_t)(nblock0 + n) * NGROUPS + g0;
        float s = __ldg(srow + g);
        float z = __ldg(zeros + (size_t)(nblock0 + n) * NGROUPS + g0 + g);
        float rq;
        if (g < GROUPS_PER - 1) {
            float sn = __ldg(srow + g + 1);
            rq = __fdividef(s, sn);
        } else {
            rq = s;
        }
        c2s[g * NBLK + n] = z + 1024.0f;
        rqs[g * NBLK + n] = rq;
    }

    // ---- group-0 sync, then in-CTA X computation from the staged xs tile ----
    cp_wait<1>();          // weight group 0 complete
    __syncthreads();       // xs / LUT stores visible

    {
        // thread -> (g = tid>>5, m = tid&31): X_g[m] = sum of 64 fp16 x values
        const int xg_g = tid >> 5;
        const int xg_m = tid & 31;
        const char* xrow = reinterpret_cast<const char*>(xs) + xg_m * XROWB;
        const int msw = xg_m & 7;
        float sx = 0.0f, sy = 0.0f;
#pragma unroll
        for (int c = 0; c < 8; ++c) {
            int ch = (8 * xg_g + c) ^ msw;
            uint4 v = *reinterpret_cast<const uint4*>(xrow + ch * 16);
            float2 f;
            f = __half22float2(*reinterpret_cast<__half2*>(&v.x)); sx += f.x; sy += f.y;
            f = __half22float2(*reinterpret_cast<__half2*>(&v.y)); sx += f.x; sy += f.y;
            f = __half22float2(*reinterpret_cast<__half2*>(&v.z)); sx += f.x; sy += f.y;
            f = __half22float2(*reinterpret_cast<__half2*>(&v.w)); sx += f.x; sy += f.y;
        }
        xsum[tid] = sx + sy;
    }
    __syncthreads();       // xsum visible to all warps

    // lane geometry (v11)
    const unsigned xs_base = smem_u32(xs);
    const unsigned xrow0 = xs_base + (unsigned)((l & 15) * XROWB);
    const unsigned xrow1 = xrow0 + 16u * XROWB;
    const int hk = l >> 4;
    const int lw = l & 7;
    const int xw = l >> 2;
    const int wbase0 = (w * 16 + (l >> 2)) * 32 + (l & 3);
    const int wbase1 = wbase0 + 8 * 32;
    const int ncol = w * 16 + 2 * (l & 3);

    float acc[2][2][4] = {};

#pragma unroll
    for (int g = 0; g < GROUPS_PER; ++g) {
        if (g > 0) {
            if (g == GROUPS_PER - 1) cp_wait<0>(); else cp_wait<1>();
            __syncthreads();
        }

        const int bufo = (g & 1) * WGRP;

#pragma unroll
        for (int s4 = 0; s4 < 4; ++s4) {
            const int s = g * 4 + s4;          // global k16-step
            unsigned xoff = (unsigned)(((2 * s + hk) ^ lw) << 4);
            unsigned a0[4], a1[4];
            ldsm4(a0[0], a0[1], a0[2], a0[3], xrow0 + xoff);
            ldsm4(a1[0], a1[1], a1[2], a1[3], xrow1 + xoff);

            const int c0 = ((2 * s4)     ^ xw) * 4;
            const int c1 = ((2 * s4 + 1) ^ xw) * 4;
            unsigned b0[2], b1[2];
            b0[0] = dqraw(ws[bufo + wbase0 + c0]);
            b0[1] = dqraw(ws[bufo + wbase0 + c1]);
            b1[0] = dqraw(ws[bufo + wbase1 + c0]);
            b1[1] = dqraw(ws[bufo + wbase1 + c1]);

            mma16816(acc[0][0], a0, b0);
            mma16816(acc[0][1], a0, b1);
            mma16816(acc[1][0], a1, b0);
            mma16816(acc[1][1], a1, b1);
        }

        // end-of-group fixup: acc = (acc - (z+1024)*X_g[row]) * rq
        {
            const float* xg = xsum + g * 32 + (l >> 2);
            float Xv[4];
            Xv[0] = xg[0];  Xv[1] = xg[8];
            Xv[2] = xg[16]; Xv[3] = xg[24];
            const float* c2g = c2s + g * NBLK + ncol;
            const float* rqg = rqs + g * NBLK + ncol;
            float c2v[4], rqv[4];
            c2v[0] = c2g[0]; c2v[1] = c2g[1]; c2v[2] = c2g[8]; c2v[3] = c2g[9];
            rqv[0] = rqg[0]; rqv[1] = rqg[1]; rqv[2] = rqg[8]; rqv[3] = rqg[9];
#pragma unroll
            for (int tm = 0; tm < 2; ++tm)
#pragma unroll
                for (int tn = 0; tn < 2; ++tn)
#pragma unroll
                    for (int e = 0; e < 4; ++e) {
                        const float Xe = Xv[tm * 2 + (e >> 1)];
                        const float c2e = c2v[tn * 2 + (e & 1)];
                        const float rqe = rqv[tn * 2 + (e & 1)];
                        acc[tm][tn][e] = fmaf(-c2e, Xe, acc[tm][tn][e]) * rqe;
                    }
        }

        if (g < GROUPS_PER - 2) {
            __syncthreads();           // all warps done reading buffer g&1
            stage_w(g + 2, g & 1);
        }
    }

    // ---- bias: added exactly once (by the blockIdx.y==0 K-slice) ----
    if (blockIdx.y == 0) {
        const int n0 = nblock0 + w * 16 + 0 + 2 * (l & 3);
        const int n1 = nblock0 + w * 16 + 8 + 2 * (l & 3);
        float b00 = __ldg(bias + n0), b01 = __ldg(bias + n0 + 1);
        float b10 = __ldg(bias + n1), b11 = __ldg(bias + n1 + 1);
#pragma unroll
        for (int tm = 0; tm < 2; ++tm) {
            acc[tm][0][0] += b00; acc[tm][0][1] += b01;
            acc[tm][0][2] += b00; acc[tm][0][3] += b01;
            acc[tm][1][0] += b10; acc[tm][1][1] += b11;
            acc[tm][1][2] += b10; acc[tm][1][3] += b11;
        }
    }

    // ---- epilogue: K-split partials via vector reductions (out pre-zeroed) ----
#pragma unroll
    for (int tm = 0; tm < 2; ++tm) {
#pragma unroll
        for (int tn = 0; tn < 2; ++tn) {
            const int n = nblock0 + w * 16 + tn * 8 + (l & 3) * 2;
            const int m = tm * 16 + (l >> 2);
            red2(out + (size_t)m * NDIM + n,       acc[tm][tn][0], acc[tm][tn][1]);
            red2(out + (size_t)(m + 8) * NDIM + n, acc[tm][tn][2], acc[tm][tn][3]);
        }
    }
}

extern "C" void kernel_launch(void* const* d_in, const int* in_sizes, int n_in,
                              void* d_out, int out_size) {
    const float* x      = (const float*)d_in[0];
    const int*   pw     = (const int*)d_in[1];
    const float* scales = (const float*)d_in[2];
    const float* zeros  = (const float*)d_in[3];
    const float* bias   = (const float*)d_in[4];
    float* out = (float*)d_out;

    // zero accumulator surface (graph-capturable memset node); bias is added
    // by the blockIdx.y==0 CTAs inside gptq_main.
    cudaMemsetAsync(out, 0, (size_t)MM * NDIM * sizeof(float));

    cudaFuncSetAttribute(gptq_main, cudaFuncAttributeMaxDynamicSharedMemorySize,
                         SMEM_TOTAL);
    dim3 grid(NDIM / NBLK, KSPLIT);
    gptq_main<<<grid, NTHREADS, SMEM_TOTAL>>>(x, pw, scales, zeros, bias, out);
}

// round 16
// speedup vs baseline: 1.0861x; 1.0109x over previous
#include <cuda_runtime.h>
#include <cuda_fp16.h>

// GPTQ int4 dequant GEMM via HMMA: out[32,8192] = x @ dequant(W)^T + bias
// M=32, K=8192, N=8192, group=64. packed int32 element = one byte = 2 k-nibbles.
// v16 = v15 with the in-CTA X_g[m] pass HOISTED before cp_wait so it overlaps
// the group-0/1 weight cp.async flight (v15 serialized wait->X and lost 1.8us).
//   - out zeroed by cudaMemsetAsync; bias added by blockIdx.y==0 CTAs.
//   - v11 mainloop verbatim (raw biased nibbles 1024+q, running rescale fixup,
//     XOR swizzle, 2-deep ring, 3 CTAs/SM).

#define MM 32
#define KDIM 8192
#define NDIM 8192
#define GS 64
#define NGROUPS 128
#define NTHREADS 256
#define NBLK 128           // n per CTA
#define KSPLIT 16
#define KPER 512           // k per CTA
#define GROUPS_PER 8       // KPER / GS
#define WGRP 4096          // int32 per group buffer: 128 rows * 32 int32
#define WS_BYTES (2 * WGRP * 4)          // 32768
#define XROWB 1024         // bytes per xs row (512 k * 2B, swizzled, no pad)
#define XS_BYTES (MM * XROWB)            // 32768
#define SMEM_TOTAL (WS_BYTES + XS_BYTES + 1024 + 2 * GROUPS_PER * NBLK * 4) // 74752

__device__ __forceinline__ unsigned smem_u32(const void* p) {
    unsigned a;
    asm("{ .reg .u64 t; cvta.to.shared.u64 t, %1; cvt.u32.u64 %0, t; }"
        : "=r"(a) : "l"(p));
    return a;
}
__device__ __forceinline__ void cp_async16(unsigned saddr, const void* gptr) {
    asm volatile("cp.async.cg.shared.global [%0], [%1], 16;\n"
                 :: "r"(saddr), "l"(gptr));
}
__device__ __forceinline__ void cp_commit() {
    asm volatile("cp.async.commit_group;\n" ::: "memory");
}
template <int N>
__device__ __forceinline__ void cp_wait() {
    asm volatile("cp.async.wait_group %0;\n" :: "n"(N) : "memory");
}
__device__ __forceinline__ void ldsm4(unsigned& r0, unsigned& r1,
                                      unsigned& r2, unsigned& r3, unsigned a) {
    asm volatile("ldmatrix.sync.aligned.m8n8.x4.shared.b16 {%0,%1,%2,%3}, [%4];"
                 : "=r"(r0), "=r"(r1), "=r"(r2), "=r"(r3) : "r"(a));
}
__device__ __forceinline__ void mma16816(float d[4], const unsigned a[4],
                                         const unsigned b[2]) {
    asm volatile(
        "mma.sync.aligned.m16n8k16.row.col.f32.f16.f16.f32 "
        "{%0,%1,%2,%3}, {%4,%5,%6,%7}, {%8,%9}, {%0,%1,%2,%3};"
        : "+f"(d[0]), "+f"(d[1]), "+f"(d[2]), "+f"(d[3])
        : "r"(a[0]), "r"(a[1]), "r"(a[2]), "r"(a[3]), "r"(b[0]), "r"(b[1]));
}
__device__ __forceinline__ void red2(float* p, float a, float b) {
    asm volatile("red.global.add.v2.f32 [%0], {%1, %2};"
                 :: "l"(p), "f"(a), "f"(b) : "memory");
}
// raw biased dequant: byte b -> fp16x2 {lo = 1024+lo_nib, hi = 1024+hi_nib}. Exact.
__device__ __forceinline__ unsigned dqraw(int b) {
    unsigned t = (unsigned)b | ((unsigned)b << 12);
    return (t & 0x000F000Fu) | 0x64006400u;
}

extern __shared__ char smem_raw[];

__global__ void __launch_bounds__(NTHREADS, 3)
gptq_main(const float* __restrict__ x, const int* __restrict__ pw,
          const float* __restrict__ scales, const float* __restrict__ zeros,
          const float* __restrict__ bias, float* __restrict__ out)
{
    int* ws = reinterpret_cast<int*>(smem_raw);                        // [2][128][32], swizzled
    __half* xs = reinterpret_cast<__half*>(smem_raw + WS_BYTES);       // [32][512], swizzled
    float* xsum = reinterpret_cast<float*>(smem_raw + WS_BYTES + XS_BYTES); // [8][32]
    float* c2s = xsum + GROUPS_PER * 32;                               // [8][128] z+1024
    float* rqs = c2s + GROUPS_PER * NBLK;                              // [8][128] ratio

    const int tid = threadIdx.x;
    const int w = tid >> 5;
    const int l = tid & 31;
    const int nblock0 = blockIdx.x * NBLK;
    const int k0 = blockIdx.y * KPER;
    const int g0 = blockIdx.y * GROUPS_PER;

    const unsigned ws_base = smem_u32(ws);

    // weight staging (v11 geometry): thread -> (row = tid>>3 + 32i, ch = tid&7),
    // swizzled chunk = ch ^ (row&7).
    const int s_ch  = tid & 7;
    const int s_row = tid >> 3;
    const int s_swz = s_ch ^ (s_row & 7);

    auto stage_w = [&](int g, int b) {
        const int* gsrc = pw + ((k0 + g * GS) >> 1) + s_ch * 4;
        unsigned sdst = ws_base + (unsigned)(b * WGRP * 4 + s_row * 128 + s_swz * 16);
#pragma unroll
        for (int i = 0; i < 4; ++i)
            cp_async16(sdst + (unsigned)(i * 32 * 128),
                       gsrc + (size_t)(nblock0 + s_row + i * 32) * (KDIM / 2));
        cp_commit();
    };
    stage_w(0, 0);
    stage_w(1, 1);

    // ---- stage x: fp32 -> fp16, swizzled 1024B rows (chunk16 ^= m&7) ----
    {
#pragma unroll
        for (int i = 0; i < 16; ++i) {
            int lin = tid + i * NTHREADS;  // 0..4095 float4s
            int v = lin & 127;             // float4 idx along k (8B unit)
            int m = lin >> 7;
            float4 xv = *reinterpret_cast<const float4*>(x + (size_t)m * KDIM + k0 + 4 * v);
            __half2 h0 = __floats2half2_rn(xv.x, xv.y);
            __half2 h1 = __floats2half2_rn(xv.z, xv.w);
            uint2 pr;
            pr.x = *reinterpret_cast<unsigned*>(&h0);
            pr.y = *reinterpret_cast<unsigned*>(&h1);
            unsigned byte_off = (unsigned)(m * XROWB + (((v >> 1) ^ (m & 7)) << 4) + (v & 1) * 8);
            *reinterpret_cast<uint2*>(reinterpret_cast<char*>(xs) + byte_off) = pr;
        }
    }

    // ---- scale/zero LUTs: c2[g][n] = z+1024; rq = s_g/s_{g+1} (g<7), s_7 (g==7) ----
#pragma unroll
    for (int i = 0; i < 4; ++i) {
        int lin = tid + i * NTHREADS;   // 0..1023
        int g = lin & 7;
        int n = lin >> 3;               // 0..127
        const float* srow = scales + (size_t)(nblock0 + n) * NGROUPS + g0;
        float s = __ldg(srow + g);
        float z = __ldg(zeros + (size_t)(nblock0 + n) * NGROUPS + g0 + g);
        float rq;
        if (g < GROUPS_PER - 1) {
            float sn = __ldg(srow + g + 1);
            rq = __fdividef(s, sn);
        } else {
            rq = s;
        }
        c2s[g * NBLK + n] = z + 1024.0f;
        rqs[g * NBLK + n] = rq;
    }

    // ---- barrier: xs (STS) visible; weights may still be in flight ----
    __syncthreads();

    // ---- in-CTA X pass, OVERLAPPED with the weight cp.async flight ----
    {
        // thread -> (g = tid>>5, m = tid&31): X_g[m] = sum of 64 fp16 x values
        const int xg_g = tid >> 5;
        const int xg_m = tid & 31;
        const char* xrow = reinterpret_cast<const char*>(xs) + xg_m * XROWB;
        const int msw = xg_m & 7;
        float sx = 0.0f, sy = 0.0f;
#pragma unroll
        for (int c = 0; c < 8; ++c) {
            int ch = (8 * xg_g + c) ^ msw;
            uint4 v = *reinterpret_cast<const uint4*>(xrow + ch * 16);
            float2 f;
            f = __half22float2(*reinterpret_cast<__half2*>(&v.x)); sx += f.x; sy += f.y;
            f = __half22float2(*reinterpret_cast<__half2*>(&v.y)); sx += f.x; sy += f.y;
            f = __half22float2(*reinterpret_cast<__half2*>(&v.z)); sx += f.x; sy += f.y;
            f = __half22float2(*reinterpret_cast<__half2*>(&v.w)); sx += f.x; sy += f.y;
        }
        xsum[tid] = sx + sy;
    }
    // NOTE: no barrier here -- the mainloop's g==0 cp_wait+__syncthreads()
    // publishes xsum to all warps before any fixup reads it.

    // lane geometry (v11)
    const unsigned xs_base = smem_u32(xs);
    const unsigned xrow0 = xs_base + (unsigned)((l & 15) * XROWB);
    const unsigned xrow1 = xrow0 + 16u * XROWB;
    const int hk = l >> 4;
    const int lw = l & 7;
    const int xw = l >> 2;
    const int wbase0 = (w * 16 + (l >> 2)) * 32 + (l & 3);
    const int wbase1 = wbase0 + 8 * 32;
    const int ncol = w * 16 + 2 * (l & 3);

    float acc[2][2][4] = {};

#pragma unroll
    for (int g = 0; g < GROUPS_PER; ++g) {
        if (g == GROUPS_PER - 1) cp_wait<0>(); else cp_wait<1>();
        __syncthreads();

        const int bufo = (g & 1) * WGRP;

#pragma unroll
        for (int s4 = 0; s4 < 4; ++s4) {
            const int s = g * 4 + s4;          // global k16-step
            unsigned xoff = (unsigned)(((2 * s + hk) ^ lw) << 4);
            unsigned a0[4], a1[4];
            ldsm4(a0[0], a0[1], a0[2], a0[3], xrow0 + xoff);
            ldsm4(a1[0], a1[1], a1[2], a1[3], xrow1 + xoff);

            const int c0 = ((2 * s4)     ^ xw) * 4;
            const int c1 = ((2 * s4 + 1) ^ xw) * 4;
            unsigned b0[2], b1[2];
            b0[0] = dqraw(ws[bufo + wbase0 + c0]);
            b0[1] = dqraw(ws[bufo + wbase0 + c1]);
            b1[0] = dqraw(ws[bufo + wbase1 + c0]);
            b1[1] = dqraw(ws[bufo + wbase1 + c1]);

            mma16816(acc[0][0], a0, b0);
            mma16816(acc[0][1], a0, b1);
            mma16816(acc[1][0], a1, b0);
            mma16816(acc[1][1], a1, b1);
        }

        // end-of-group fixup: acc = (acc - (z+1024)*X_g[row]) * rq
        {
            const float* xg = xsum + g * 32 + (l >> 2);
            float Xv[4];
            Xv[0] = xg[0];  Xv[1] = xg[8];
            Xv[2] = xg[16]; Xv[3] = xg[24];
            const float* c2g = c2s + g * NBLK + ncol;
            const float* rqg = rqs + g * NBLK + ncol;
            float c2v[4], rqv[4];
            c2v[0] = c2g[0]; c2v[1] = c2g[1]; c2v[2] = c2g[8]; c2v[3] = c2g[9];
            rqv[0] = rqg[0]; rqv[1] = rqg[1]; rqv[2] = rqg[8]; rqv[3] = rqg[9];
#pragma unroll
            for (int tm = 0; tm < 2; ++tm)
#pragma unroll
                for (int tn = 0; tn < 2; ++tn)
#pragma unroll
                    for (int e = 0; e < 4; ++e) {
                        const float Xe = Xv[tm * 2 + (e >> 1)];
                        const float c2e = c2v[tn * 2 + (e & 1)];
                        const float rqe = rqv[tn * 2 + (e & 1)];
                        acc[tm][tn][e] = fmaf(-c2e, Xe, acc[tm][tn][e]) * rqe;
                    }
        }

        if (g < GROUPS_PER - 2) {
            __syncthreads();           // all warps done reading buffer g&1
            stage_w(g + 2, g & 1);
        }
    }

    // ---- bias: added exactly once (by the blockIdx.y==0 K-slice) ----
    if (blockIdx.y == 0) {
        const int n0 = nblock0 + w * 16 + 0 + 2 * (l & 3);
        const int n1 = nblock0 + w * 16 + 8 + 2 * (l & 3);
        float b00 = __ldg(bias + n0), b01 = __ldg(bias + n0 + 1);
        float b10 = __ldg(bias + n1), b11 = __ldg(bias + n1 + 1);
#pragma unroll
        for (int tm = 0; tm < 2; ++tm) {
            acc[tm][0][0] += b00; acc[tm][0][1] += b01;
            acc[tm][0][2] += b00; acc[tm][0][3] += b01;
            acc[tm][1][0] += b10; acc[tm][1][1] += b11;
            acc[tm][1][2] += b10; acc[tm][1][3] += b11;
        }
    }

    // ---- epilogue: K-split partials via vector reductions (out pre-zeroed) ----
#pragma unroll
    for (int tm = 0; tm < 2; ++tm) {
#pragma unroll
        for (int tn = 0; tn < 2; ++tn) {
            const int n = nblock0 + w * 16 + tn * 8 + (l & 3) * 2;
            const int m = tm * 16 + (l >> 2);
            red2(out + (size_t)m * NDIM + n,       acc[tm][tn][0], acc[tm][tn][1]);
            red2(out + (size_t)(m + 8) * NDIM + n, acc[tm][tn][2], acc[tm][tn][3]);
        }
    }
}

extern "C" void kernel_launch(void* const* d_in, const int* in_sizes, int n_in,
                              void* d_out, int out_size) {
    const float* x      = (const float*)d_in[0];
    const int*   pw     = (const int*)d_in[1];
    const float* scales = (const float*)d_in[2];
    const float* zeros  = (const float*)d_in[3];
    const float* bias   = (const float*)d_in[4];
    float* out = (float*)d_out;

    // zero accumulator surface (graph-capturable memset node); bias is added
    // by the blockIdx.y==0 CTAs inside gptq_main.
    cudaMemsetAsync(out, 0, (size_t)MM * NDIM * sizeof(float));

    cudaFuncSetAttribute(gptq_main, cudaFuncAttributeMaxDynamicSharedMemorySize,
                         SMEM_TOTAL);
    dim3 grid(NDIM / NBLK, KSPLIT);
    gptq_main<<<grid, NTHREADS, SMEM_TOTAL>>>(x, pw, scales, zeros, bias, out);
}